// round 3
// baseline (speedup 1.0000x reference)
#include <cuda_runtime.h>

#define Bn 128
#define Tn 800
#define Un 64
#define Hn 256
#define Kw 10
#define Gn 20
#define An 64

#define NBLK 128
#define NTH  256

// ---------------- persistent device state / scratch ----------------
__device__ float g_W1[324 * 1024];      // [xt(3), w(64), h1(256), pad] x 4H
__device__ float g_W2[580 * 1024];      // [xt, w, h1, h2prev, pad]
__device__ float g_W3[580 * 1024];      // [xt, w, h2, h3prev, pad]
__device__ float g_b1[1024], g_b2[1024], g_b3[1024];
__device__ float g_Wh[256 * 121];       // concatenated head weights
__device__ float g_bh[121];

__device__ float g_h1[2][Bn * Hn];
__device__ float g_h2[2][Bn * Hn];
__device__ float g_c1[Bn * Hn], g_c2[Bn * Hn], g_c3[Bn * Hn];
__device__ float g_w[2][Bn * An];
__device__ float g_kappa[Bn * Kw];
__device__ float g_zero[Bn * Hn];
__device__ float g_out[Tn * Bn * Hn];   // h3 per step

__device__ unsigned g_bar_cnt = 0;
__device__ volatile unsigned g_bar_gen = 0;

// ---------------- helpers ----------------
__device__ __forceinline__ float sigm(float x) {
    return 1.0f / (1.0f + __expf(-x));
}
__device__ __forceinline__ float tanh_f(float x) {
    float xx = fminf(15.0f, fmaxf(-15.0f, x));
    float t = __expf(-2.0f * xx);
    return (1.0f - t) / (1.0f + t);
}

// All-atomic grid barrier: no plain stores on the hot path, so no
// L1-visibility race between the counter reset and the next barrier's adds.
__device__ __forceinline__ void grid_barrier() {
    __syncthreads();
    if (threadIdx.x == 0) {
        __threadfence();
        unsigned gen = g_bar_gen;
        if (atomicAdd(&g_bar_cnt, 1u) == NBLK - 1u) {
            atomicSub(&g_bar_cnt, (unsigned)NBLK);   // atomic reset to 0
            __threadfence();
            g_bar_gen = gen + 1u;                    // volatile release
        } else {
            while (g_bar_gen == gen) { __nanosleep(40); }
            __threadfence();
        }
    }
    __syncthreads();
}

// ---------------- LSTM gate+cell stage (64 CTAs, NB=8 batch/thread) ----------------
// lc in [0,64): b-tile = lc>>2 (8 batches), j-tile = lc&3 (64 hidden units)
// lane = g*8+u : thread computes gate column j = g*256 + hu for 8 batches.
template <int KT, int KP>
__device__ void lstm_stage(int lc, const float* __restrict__ x, int t,
                           const float* __restrict__ wv,
                           const float* __restrict__ hA,
                           const float* __restrict__ hB,
                           const float* __restrict__ W,
                           const float* __restrict__ bsum,
                           float* __restrict__ cst,
                           float* __restrict__ hout) {
    __shared__ __align__(16) float sbuf[8 * KP];
    const int tid = threadIdx.x;
    const int b0 = (lc >> 2) * 8;
    const int wp = tid >> 5, lane = tid & 31;
    const int g = lane >> 3, u = lane & 7;
    const int hu = (lc & 3) * 64 + wp * 8 + u;
    const int j = g * 256 + hu;

    // stage input vectors for the 8 batches into smem
    for (int idx = tid; idx < 8 * KP; idx += NTH) {
        int r = idx / KP;
        int i = idx - r * KP;
        int b = b0 + r;
        float v = 0.0f;
        if (i < 3)        v = x[(b * Tn + t) * 3 + i];
        else if (i < 67)  v = wv[b * 64 + (i - 3)];
        else if (i < 323) v = hA[(b << 8) + (i - 67)];
        else if (i < KT)  v = hB[(b << 8) + (i - 323)];
        sbuf[idx] = v;
    }
    __syncthreads();

    float acc[8];
#pragma unroll
    for (int r = 0; r < 8; r++) acc[r] = 0.0f;

    const float* Wj = W + j;
#pragma unroll 4
    for (int i4 = 0; i4 < KP / 4; i4++) {
        float w0 = Wj[(i4 * 4 + 0) * 1024];
        float w1 = Wj[(i4 * 4 + 1) * 1024];
        float w2 = Wj[(i4 * 4 + 2) * 1024];
        float w3 = Wj[(i4 * 4 + 3) * 1024];
#pragma unroll
        for (int r = 0; r < 8; r++) {
            float4 iv = reinterpret_cast<const float4*>(sbuf + r * KP)[i4];
            acc[r] = fmaf(iv.x, w0, acc[r]);
            acc[r] = fmaf(iv.y, w1, acc[r]);
            acc[r] = fmaf(iv.z, w2, acc[r]);
            acc[r] = fmaf(iv.w, w3, acc[r]);
        }
    }

    const float bias = bsum[j];
#pragma unroll
    for (int r = 0; r < 8; r++) {
        float v = acc[r] + bias;
        // gather the 4 gates of hidden unit hu (lanes u, 8+u, 16+u, 24+u)
        float vi = __shfl_sync(0xffffffffu, v, u);
        float vf = __shfl_sync(0xffffffffu, v, 8 + u);
        float vg = __shfl_sync(0xffffffffu, v, 16 + u);
        float vo = __shfl_sync(0xffffffffu, v, 24 + u);
        int b = b0 + r;
        float cp = cst[(b << 8) + hu];
        float ig = sigm(vi), fg = sigm(vf), og = sigm(vo);
        float gg = tanh_f(vg);
        float cn = fmaf(fg, cp, ig * gg);
        float hn = og * tanh_f(cn);
        if (g == 0) {
            cst[(b << 8) + hu] = cn;
            hout[(b << 8) + hu] = hn;
        }
    }
}

// ---------------- attention stage (64 CTAs, 2 batches each) ----------------
__device__ void attn_stage(int ai, const float* __restrict__ h1,
                           float* __restrict__ wout,
                           const int* __restrict__ cidx,
                           const float* __restrict__ Ww,
                           const float* __restrict__ bw) {
    __shared__ float aw[2][30];
    __shared__ float kapn[2][10];
    __shared__ float phi_s[2][64];
    __shared__ int cs[2][64];
    const int half = threadIdx.x >> 7;
    const int tt = threadIdx.x & 127;
    const int b = ai * 2 + half;

    if (tt < 30) {
        float z = bw[tt];
        const float* hr = h1 + (b << 8);
#pragma unroll 8
        for (int i = 0; i < 256; i++) z = fmaf(hr[i], Ww[i * 30 + tt], z);
        aw[half][tt] = __expf(z);
    }
    if (tt < 64) cs[half][tt] = cidx[b * 64 + tt];
    __syncthreads();

    if (tt < 10) {
        float kn = fmaf(0.1f, aw[half][20 + tt], g_kappa[b * 10 + tt]);
        g_kappa[b * 10 + tt] = kn;
        kapn[half][tt] = kn;
    }
    __syncthreads();

    if (tt < 64) {
        float uu = (float)tt;
        float phi = 0.0f;
#pragma unroll
        for (int k = 0; k < 10; k++) {
            float d = kapn[half][k] - uu;
            phi = fmaf(aw[half][k], __expf(-aw[half][10 + k] * d * d), phi);
        }
        phi_s[half][tt] = phi;
    }
    __syncthreads();

    if (tt < 64) {
        float s = 0.0f;
        for (int uix = 0; uix < 64; uix++)
            if (cs[half][uix] == tt) s += phi_s[half][uix];
        wout[b * 64 + tt] = s;
    }
}

// ---------------- persistent RNN kernel ----------------
__global__ void __launch_bounds__(NTH)
rnn_kernel(const float* __restrict__ x, const int* __restrict__ cidx,
           const float* __restrict__ Ww, const float* __restrict__ bw) {
    const int cta = blockIdx.x;
    const int tid = threadIdx.x;

    // re-init recurrent state every launch (graph replays!)
    {
        int g0 = cta * NTH + tid;
        int gsz = NBLK * NTH;
        for (int p = g0; p < Bn * Hn; p += gsz) {
            g_h1[0][p] = 0.f; g_h1[1][p] = 0.f;
            g_h2[0][p] = 0.f; g_h2[1][p] = 0.f;
            g_c1[p] = 0.f; g_c2[p] = 0.f; g_c3[p] = 0.f;
            g_zero[p] = 0.f;
        }
        for (int p = g0; p < Bn * An; p += gsz) { g_w[0][p] = 0.f; g_w[1][p] = 1.0f; }
        for (int p = g0; p < Bn * Kw; p += gsz) g_kappa[p] = 0.f;
    }
    grid_barrier();

    // prologue: LSTM1(0) reads w(-1)=ones (g_w[1]), h1(-1)=g_h1[1]=0 -> h1(0)=g_h1[0]
    if (cta < 64)
        lstm_stage<323, 324>(cta, x, 0, g_w[1], g_h1[1], (const float*)0,
                             g_W1, g_b1, g_c1, g_h1[0]);
    grid_barrier();
    // Attn(0): h1(0) -> w(0)=g_w[0], kappa
    if (cta >= 64)
        attn_stage(cta - 64, g_h1[0], g_w[0], cidx, Ww, bw);
    grid_barrier();

    for (int t = 0; t < Tn; t++) {
        const int p = t & 1, pn = (t + 1) & 1;
        const float* wcur = g_w[p];

        // Phase A: LSTM2(t) || LSTM1(t+1)
        if (cta < 64) {
            lstm_stage<579, 580>(cta, x, t, wcur, g_h1[p], g_h2[pn],
                                 g_W2, g_b2, g_c2, g_h2[p]);
        } else if (t + 1 < Tn) {
            lstm_stage<323, 324>(cta - 64, x, t + 1, wcur, g_h1[p], (const float*)0,
                                 g_W1, g_b1, g_c1, g_h1[pn]);
        }
        grid_barrier();

        // Phase B: LSTM3(t) || Attn(t+1)
        if (cta < 64) {
            const float* h3prev = (t > 0) ? (g_out + (t - 1) * Bn * Hn) : g_zero;
            lstm_stage<579, 580>(cta, x, t, wcur, g_h2[p], h3prev,
                                 g_W3, g_b3, g_c3, g_out + t * Bn * Hn);
        } else if (t + 1 < Tn) {
            attn_stage(cta - 64, g_h1[pn], g_w[pn], cidx, Ww, bw);
        }
        grid_barrier();
    }
}

// ---------------- weight pre-pack kernel ----------------
__global__ void prep_kernel(
    const float* Wih1, const float* Whh1, const float* bih1, const float* bhh1,
    const float* Wih2, const float* Whh2, const float* bih2, const float* bhh2,
    const float* Wih3, const float* Whh3, const float* bih3, const float* bhh3,
    const float* We, const float* be, const float* Wpi, const float* bpi,
    const float* Wmu1, const float* bmu1, const float* Wmu2, const float* bmu2,
    const float* Ws1, const float* bs1, const float* Ws2, const float* bs2,
    const float* Wrho, const float* brho) {
    int g0 = blockIdx.x * blockDim.x + threadIdx.x;
    int gsz = gridDim.x * blockDim.x;

    for (int pidx = g0; pidx < 324 * 1024; pidx += gsz) {
        int i = pidx >> 10, j = pidx & 1023;
        float v = 0.f;
        if (i < 67) v = Wih1[i * 1024 + j];
        else if (i < 323) v = Whh1[(i - 67) * 1024 + j];
        g_W1[pidx] = v;
    }
    for (int pidx = g0; pidx < 580 * 1024; pidx += gsz) {
        int i = pidx >> 10, j = pidx & 1023;
        float v2 = 0.f, v3 = 0.f;
        if (i < 323) { v2 = Wih2[i * 1024 + j]; v3 = Wih3[i * 1024 + j]; }
        else if (i < 579) {
            v2 = Whh2[(i - 323) * 1024 + j];
            v3 = Whh3[(i - 323) * 1024 + j];
        }
        g_W2[pidx] = v2;
        g_W3[pidx] = v3;
    }
    for (int pidx = g0; pidx < 1024; pidx += gsz) {
        g_b1[pidx] = bih1[pidx] + bhh1[pidx];
        g_b2[pidx] = bih2[pidx] + bhh2[pidx];
        g_b3[pidx] = bih3[pidx] + bhh3[pidx];
    }
    for (int pidx = g0; pidx < 256 * 121; pidx += gsz) {
        int i = pidx / 121, col = pidx - i * 121;
        float v;
        if (col == 0)       v = We[i];
        else if (col < 21)  v = Wpi[i * 20 + (col - 1)];
        else if (col < 41)  v = Wmu1[i * 20 + (col - 21)];
        else if (col < 61)  v = Wmu2[i * 20 + (col - 41)];
        else if (col < 81)  v = Ws1[i * 20 + (col - 61)];
        else if (col < 101) v = Ws2[i * 20 + (col - 81)];
        else                v = Wrho[i * 20 + (col - 101)];
        g_Wh[pidx] = v;
    }
    for (int col = g0; col < 121; col += gsz) {
        float v;
        if (col == 0)       v = be[0];
        else if (col < 21)  v = bpi[col - 1];
        else if (col < 41)  v = bmu1[col - 21];
        else if (col < 61)  v = bmu2[col - 41];
        else if (col < 81)  v = bs1[col - 61];
        else if (col < 101) v = bs2[col - 81];
        else                v = brho[col - 101];
        g_bh[col] = v;
    }
}

// ---------------- MDN heads kernel ----------------
__global__ void __launch_bounds__(128)
heads_kernel(float* __restrict__ out) {
    __shared__ __align__(16) float hs[32 * 256];
    __shared__ float pz[32][20];
    const int r0 = blockIdx.x * 32;
    const int tid = threadIdx.x;

    {   // load 32 h3 rows
        const float4* src = reinterpret_cast<const float4*>(g_out + r0 * 256);
        float4* dst = reinterpret_cast<float4*>(hs);
        for (int pidx = tid; pidx < 32 * 64; pidx += 128) dst[pidx] = src[pidx];
    }
    __syncthreads();

    const int j = tid;
    float acc[32];
    if (j < 121) {
#pragma unroll
        for (int r = 0; r < 32; r++) acc[r] = 0.0f;
#pragma unroll 2
        for (int i4 = 0; i4 < 64; i4++) {
            float w0 = g_Wh[(i4 * 4 + 0) * 121 + j];
            float w1 = g_Wh[(i4 * 4 + 1) * 121 + j];
            float w2 = g_Wh[(i4 * 4 + 2) * 121 + j];
            float w3 = g_Wh[(i4 * 4 + 3) * 121 + j];
#pragma unroll
            for (int r = 0; r < 32; r++) {
                float4 hv = reinterpret_cast<const float4*>(hs + r * 256)[i4];
                acc[r] = fmaf(hv.x, w0, fmaf(hv.y, w1, fmaf(hv.z, w2, fmaf(hv.w, w3, acc[r]))));
            }
        }
        float bias = g_bh[j];
#pragma unroll
        for (int r = 0; r < 32; r++) acc[r] += bias;
        if (j >= 1 && j < 21)
            for (int r = 0; r < 32; r++) pz[r][j - 1] = acc[r];
    }
    __syncthreads();

    if (j < 121) {
        const int TB = Tn * Bn;
        float* es  = out;
        float* pi  = out + TB;
        float* mu1 = out + TB + TB * 20;
        float* mu2 = mu1 + TB * 20;
        float* s1  = mu2 + TB * 20;
        float* s2  = s1 + TB * 20;
        float* rh  = s2 + TB * 20;
        for (int r = 0; r < 32; r++) {
            int gr = r0 + r;
            float z = acc[r];
            if (j == 0) {
                es[gr] = 1.0f / (1.0f + __expf(z));
            } else if (j < 21) {
                float m = -1e30f;
                for (int k = 0; k < 20; k++) m = fmaxf(m, pz[r][k]);
                float s = 0.f;
                for (int k = 0; k < 20; k++) s += __expf(pz[r][k] - m);
                pi[gr * 20 + (j - 1)] = __expf(z - m) / s;
            } else if (j < 41) {
                mu1[gr * 20 + (j - 21)] = z;
            } else if (j < 61) {
                mu2[gr * 20 + (j - 41)] = z;
            } else if (j < 81) {
                s1[gr * 20 + (j - 61)] = __expf(z);
            } else if (j < 101) {
                s2[gr * 20 + (j - 81)] = __expf(z);
            } else {
                rh[gr * 20 + (j - 101)] = tanh_f(z);
            }
        }
    }
}

// ---------------- launch ----------------
extern "C" void kernel_launch(void* const* d_in, const int* in_sizes, int n_in,
                              void* d_out, int out_size) {
    const float* x    = (const float*)d_in[0];
    const int*   c    = (const int*)d_in[1];
    const float* Wih1 = (const float*)d_in[2];
    const float* Whh1 = (const float*)d_in[3];
    const float* bih1 = (const float*)d_in[4];
    const float* bhh1 = (const float*)d_in[5];
    const float* Wih2 = (const float*)d_in[6];
    const float* Whh2 = (const float*)d_in[7];
    const float* bih2 = (const float*)d_in[8];
    const float* bhh2 = (const float*)d_in[9];
    const float* Wih3 = (const float*)d_in[10];
    const float* Whh3 = (const float*)d_in[11];
    const float* bih3 = (const float*)d_in[12];
    const float* bhh3 = (const float*)d_in[13];
    const float* Ww   = (const float*)d_in[14];
    const float* bw   = (const float*)d_in[15];
    const float* We   = (const float*)d_in[16];
    const float* be   = (const float*)d_in[17];
    const float* Wpi  = (const float*)d_in[18];
    const float* bpi  = (const float*)d_in[19];
    const float* Wmu1 = (const float*)d_in[20];
    const float* bmu1 = (const float*)d_in[21];
    const float* Wmu2 = (const float*)d_in[22];
    const float* bmu2 = (const float*)d_in[23];
    const float* Ws1  = (const float*)d_in[24];
    const float* bs1  = (const float*)d_in[25];
    const float* Ws2  = (const float*)d_in[26];
    const float* bs2  = (const float*)d_in[27];
    const float* Wrho = (const float*)d_in[28];
    const float* brho = (const float*)d_in[29];

    prep_kernel<<<512, 256>>>(Wih1, Whh1, bih1, bhh1,
                              Wih2, Whh2, bih2, bhh2,
                              Wih3, Whh3, bih3, bhh3,
                              We, be, Wpi, bpi, Wmu1, bmu1, Wmu2, bmu2,
                              Ws1, bs1, Ws2, bs2, Wrho, brho);
    rnn_kernel<<<NBLK, NTH>>>(x, c, Ww, bw);
    heads_kernel<<<(Tn * Bn) / 32, 128>>>((float*)d_out);
}